// round 2
// baseline (speedup 1.0000x reference)
#include <cuda_runtime.h>
#include <math.h>

// ---------------- problem constants ----------------
#define NB    32          // batch
#define LSEQ  192         // patches
#define SEQF  193         // with cls
#define DM    384         // d_model
#define DI    768         // d_inner
#define DS    16          // d_state
#define DTRK  24          // dt_rank
#define XPD   56          // dt_rank + 2*d_state
#define ROWS  (NB*LSEQ)   // 6144

// ---------------- scratch layout (floats) ----------------
__device__ float g_scratch[35733504];

#define OFF_PR     0
#define OFF_XLN    2359296
#define OFF_XZ     4718592
#define OFF_XC     14155776
#define OFF_XDBL   18874368
#define OFF_DT     19218432
#define OFF_Y      23937024
#define OFF_CAT    28655616
#define OFF_FUSED  33374208

// ---------------- packed f32x2 helpers ----------------
__device__ __forceinline__ void ffma2(unsigned long long &d,
                                      unsigned long long a,
                                      unsigned long long b)
{
    asm("fma.rn.f32x2 %0, %1, %2, %0;" : "+l"(d) : "l"(a), "l"(b));
}
__device__ __forceinline__ unsigned long long pack2(float x, float y)
{
    unsigned long long r;
    asm("mov.b64 %0, {%1, %2};" : "=l"(r) : "f"(x), "f"(y));
    return r;
}
__device__ __forceinline__ void unpack2(unsigned long long v, float &x, float &y)
{
    asm("mov.b64 {%0, %1}, %2;" : "=f"(x), "=f"(y) : "l"(v));
}

// ---------------- gather: pr[b,t,:] = x[b, 1+scan_idx[t], :] ----------------
__global__ void gather_kernel(const float* __restrict__ X,
                              const int* __restrict__ scan_idx,
                              float* __restrict__ PR)
{
    int idx = blockIdx.x * blockDim.x + threadIdx.x;   // over ROWS*DM
    if (idx >= ROWS * DM) return;
    int c = idx % DM;
    int t = (idx / DM) % LSEQ;
    int b = idx / (DM * LSEQ);
    int src = scan_idx[t];
    PR[idx] = X[((size_t)b * SEQF + 1 + src) * DM + c];
}

// ---------------- layernorm over DM=384, one block (128 thr) per row ----------------
__global__ __launch_bounds__(128) void ln_kernel(const float* __restrict__ X,
                                                 const float* __restrict__ G,
                                                 const float* __restrict__ Bb,
                                                 float* __restrict__ Y)
{
    int row = blockIdx.x;
    const float* x = X + (size_t)row * DM;
    float v[3]; float s = 0.f, ss = 0.f;
    #pragma unroll
    for (int i = 0; i < 3; i++) {
        v[i] = x[threadIdx.x + i * 128];
        s += v[i]; ss += v[i] * v[i];
    }
    __shared__ float sh_s[4], sh_ss[4];
    #pragma unroll
    for (int o = 16; o; o >>= 1) {
        s  += __shfl_down_sync(0xffffffffu, s,  o);
        ss += __shfl_down_sync(0xffffffffu, ss, o);
    }
    int wid = threadIdx.x >> 5, lid = threadIdx.x & 31;
    if (lid == 0) { sh_s[wid] = s; sh_ss[wid] = ss; }
    __syncthreads();
    float ts = sh_s[0] + sh_s[1] + sh_s[2] + sh_s[3];
    float tss = sh_ss[0] + sh_ss[1] + sh_ss[2] + sh_ss[3];
    float mean = ts * (1.f / DM);
    float var = tss * (1.f / DM) - mean * mean;
    float rstd = rsqrtf(var + 1e-5f);
    float* y = Y + (size_t)row * DM;
    #pragma unroll
    for (int i = 0; i < 3; i++) {
        int c = threadIdx.x + i * 128;
        y[c] = (v[i] - mean) * rstd * G[c] + Bb[c];
    }
}

// ---------------- SGEMM via packed FFMA2: C[M,N] = A[M,K] @ W[N,K]^T (+epilogue) ----------------
// Requires: M % 128 == 0, N % 128 == 0, K % 8 == 0, all row strides % 4 == 0.
// EPI: 0 = none, 1 = +bias, 2 = +bias then softplus, 3 = +residual R
template<int EPI>
__global__ __launch_bounds__(256, 2) void sgemm128(
    const float* __restrict__ A, int lda,
    const float* __restrict__ W, int K,
    const float* __restrict__ bias,
    const float* __restrict__ R, int ldr,
    float* __restrict__ C, int ldc)
{
    __shared__ float As2[8][256];   // duplicated A: As2[k][2r] = As2[k][2r+1] = A[row r]
    __shared__ float Ws[8][128];
    int tid = threadIdx.x;
    int rowBase = blockIdx.y * 128;
    int colBase = blockIdx.x * 128;
    int ty = tid >> 4, tx = tid & 15;

    int arow = tid >> 1;
    int ak   = (tid & 1) * 4;

    unsigned long long acc[8][4];
    #pragma unroll
    for (int i = 0; i < 8; i++)
        #pragma unroll
        for (int q = 0; q < 4; q++) acc[i][q] = 0ull;

    const float* Aptr = A + (size_t)(rowBase + arow) * lda + ak;
    const float* Wptr = W + (size_t)(colBase + arow) * K + ak;

    for (int k0 = 0; k0 < K; k0 += 8) {
        float4 av = *(const float4*)(Aptr + k0);
        float4 wv = *(const float4*)(Wptr + k0);
        __syncthreads();
        // duplicated A stores (64-bit)
        *(unsigned long long*)&As2[ak+0][2*arow] = pack2(av.x, av.x);
        *(unsigned long long*)&As2[ak+1][2*arow] = pack2(av.y, av.y);
        *(unsigned long long*)&As2[ak+2][2*arow] = pack2(av.z, av.z);
        *(unsigned long long*)&As2[ak+3][2*arow] = pack2(av.w, av.w);
        Ws[ak+0][arow] = wv.x; Ws[ak+1][arow] = wv.y;
        Ws[ak+2][arow] = wv.z; Ws[ak+3][arow] = wv.w;
        __syncthreads();
        #pragma unroll
        for (int k = 0; k < 8; k++) {
            // a pairs for i = 0..7 (each 64-bit lane = {a_i, a_i})
            ulonglong2 ap01 = *(const ulonglong2*)&As2[k][ty*16 + 0];
            ulonglong2 ap23 = *(const ulonglong2*)&As2[k][ty*16 + 4];
            ulonglong2 ap45 = *(const ulonglong2*)&As2[k][ty*16 + 8];
            ulonglong2 ap67 = *(const ulonglong2*)&As2[k][ty*16 + 12];
            // w pairs: 8 cols = 4 packed pairs
            ulonglong2 w01 = *(const ulonglong2*)&Ws[k][tx*8 + 0];
            ulonglong2 w23 = *(const ulonglong2*)&Ws[k][tx*8 + 4];
            unsigned long long ap[8] = {ap01.x, ap01.y, ap23.x, ap23.y,
                                        ap45.x, ap45.y, ap67.x, ap67.y};
            #pragma unroll
            for (int i = 0; i < 8; i++) {
                ffma2(acc[i][0], ap[i], w01.x);
                ffma2(acc[i][1], ap[i], w01.y);
                ffma2(acc[i][2], ap[i], w23.x);
                ffma2(acc[i][3], ap[i], w23.y);
            }
        }
    }
    #pragma unroll
    for (int i = 0; i < 8; i++) {
        int row = rowBase + ty * 8 + i;
        #pragma unroll
        for (int q = 0; q < 4; q++) {
            int col = colBase + tx * 8 + 2 * q;
            float v0, v1;
            unpack2(acc[i][q], v0, v1);
            if (EPI == 1 || EPI == 2) { v0 += bias[col]; v1 += bias[col + 1]; }
            if (EPI == 2) {
                v0 = (v0 > 20.f) ? v0 : log1pf(__expf(v0));
                v1 = (v1 > 20.f) ? v1 : log1pf(__expf(v1));
            }
            if (EPI == 3) {
                v0 += R[(size_t)row * ldr + col];
                v1 += R[(size_t)row * ldr + col + 1];
            }
            C[(size_t)row * ldc + col]     = v0;
            C[(size_t)row * ldc + col + 1] = v1;
        }
    }
}

// ---------------- small-N GEMM (x_proj: N=56, K=768): BM=32, BN=64, BK=16 ----------------
__global__ __launch_bounds__(256) void sgemm_s(
    const float* __restrict__ A, int lda,
    const float* __restrict__ W, int K,
    float* __restrict__ C, int ldc, int N)
{
    __shared__ float As[16][32];
    __shared__ float Ws[16][64];
    int tid = threadIdx.x;
    int rowBase = blockIdx.y * 32;
    int colBase = blockIdx.x * 64;
    int ty = tid >> 4, tx = tid & 15;
    float acc[2][4] = {{0.f,0.f,0.f,0.f},{0.f,0.f,0.f,0.f}};
    int wn = tid >> 2, wk = (tid & 3) * 4;
    bool wv = (colBase + wn) < N;

    for (int k0 = 0; k0 < K; k0 += 16) {
        __syncthreads();
        #pragma unroll
        for (int i = tid; i < 512; i += 256) {
            int r = i >> 4, k = i & 15;
            As[k][r] = A[(size_t)(rowBase + r) * lda + k0 + k];
        }
        float4 wvv = wv ? *(const float4*)&W[(size_t)(colBase + wn) * K + k0 + wk]
                        : make_float4(0.f,0.f,0.f,0.f);
        Ws[wk+0][wn] = wvv.x; Ws[wk+1][wn] = wvv.y;
        Ws[wk+2][wn] = wvv.z; Ws[wk+3][wn] = wvv.w;
        __syncthreads();
        #pragma unroll
        for (int k = 0; k < 16; k++) {
            float a0 = As[k][ty], a1 = As[k][ty + 16];
            float4 w4 = *(const float4*)&Ws[k][tx*4];
            acc[0][0] = fmaf(a0, w4.x, acc[0][0]);
            acc[0][1] = fmaf(a0, w4.y, acc[0][1]);
            acc[0][2] = fmaf(a0, w4.z, acc[0][2]);
            acc[0][3] = fmaf(a0, w4.w, acc[0][3]);
            acc[1][0] = fmaf(a1, w4.x, acc[1][0]);
            acc[1][1] = fmaf(a1, w4.y, acc[1][1]);
            acc[1][2] = fmaf(a1, w4.z, acc[1][2]);
            acc[1][3] = fmaf(a1, w4.w, acc[1][3]);
        }
    }
    #pragma unroll
    for (int i = 0; i < 2; i++) {
        int row = rowBase + ty + i * 16;
        #pragma unroll
        for (int j = 0; j < 4; j++) {
            int col = colBase + tx * 4 + j;
            if (col < N) C[(size_t)row * ldc + col] = acc[i][j];
        }
    }
}

// ---------------- causal depthwise conv (k=4) + SiLU; dir-aware ----------------
__global__ void conv_kernel(const float* __restrict__ XZ,
                            const float* __restrict__ Wc,
                            const float* __restrict__ Bc,
                            float* __restrict__ XC, int dir)
{
    int idx = blockIdx.x * blockDim.x + threadIdx.x;   // ROWS*DI
    if (idx >= ROWS * DI) return;
    int d = idx % DI;
    int t = (idx / DI) % LSEQ;
    int b = idx / (DI * LSEQ);
    const float* xm = XZ + (size_t)b * LSEQ * (2 * DI) + d;
    float acc = Bc[d];
    #pragma unroll
    for (int j = 0; j < 4; j++) {
        int tt = (dir == 0) ? (t - 3 + j) : (t + 3 - j);
        if (tt >= 0 && tt < LSEQ)
            acc = fmaf(Wc[d * 4 + j], xm[(size_t)tt * (2 * DI)], acc);
    }
    acc = acc / (1.f + __expf(-acc));   // silu
    XC[idx] = acc;
}

// ---------------- selective scan, fused with +u*D and *silu(z) ----------------
__global__ __launch_bounds__(256) void scan_kernel(
    const float* __restrict__ XC,
    const float* __restrict__ DT,
    const float* __restrict__ XDBL,
    const float* __restrict__ XZ,
    const float* __restrict__ Alog,
    const float* __restrict__ Dp,
    float* __restrict__ Y, int dir)
{
    __shared__ float Bs[LSEQ][DS];
    __shared__ float Cs[LSEQ][DS];
    int b = blockIdx.x;
    int d = blockIdx.y * 256 + threadIdx.x;

    const float* xd = XDBL + (size_t)b * LSEQ * XPD;
    for (int i = threadIdx.x; i < LSEQ * DS; i += 256) {
        int t = i / DS, n = i % DS;
        Bs[t][n] = xd[t * XPD + DTRK + n];
        Cs[t][n] = xd[t * XPD + DTRK + DS + n];
    }
    __syncthreads();

    float A[DS];
    #pragma unroll
    for (int n = 0; n < DS; n++) A[n] = -__expf(Alog[d * DS + n]);
    float Dd = Dp[d];
    float h[DS];
    #pragma unroll
    for (int n = 0; n < DS; n++) h[n] = 0.f;

    const float* ub  = XC + (size_t)b * LSEQ * DI + d;
    const float* dtb = DT + (size_t)b * LSEQ * DI + d;
    const float* zb  = XZ + (size_t)b * LSEQ * (2 * DI) + DI + d;
    float* yb = Y + (size_t)b * LSEQ * DI + d;

    for (int s = 0; s < LSEQ; s++) {
        int t = dir ? (LSEQ - 1 - s) : s;
        float dtv = dtb[(size_t)t * DI];
        float u   = ub[(size_t)t * DI];
        float du  = dtv * u;
        float accv = 0.f;
        #pragma unroll
        for (int n = 0; n < DS; n++) {
            float dA = __expf(dtv * A[n]);
            h[n] = fmaf(dA, h[n], du * Bs[t][n]);
            accv = fmaf(h[n], Cs[t][n], accv);
        }
        float z = zb[(size_t)t * (2 * DI)];
        float sz = z / (1.f + __expf(-z));
        yb[(size_t)t * DI] = (accv + u * Dd) * sz;
    }
}

// ---------------- final: scatter via inv_idx + cls passthrough ----------------
__global__ void final_kernel(const float* __restrict__ X,
                             const float* __restrict__ FUSED,
                             const int* __restrict__ inv_idx,
                             float* __restrict__ OUT)
{
    int idx = blockIdx.x * blockDim.x + threadIdx.x;   // NB*SEQF*DM
    if (idx >= NB * SEQF * DM) return;
    int c = idx % DM;
    int s = (idx / DM) % SEQF;
    int b = idx / (DM * SEQF);
    if (s == 0) {
        OUT[idx] = X[idx];
    } else {
        int src = inv_idx[s - 1];
        OUT[idx] = FUSED[((size_t)b * LSEQ + src) * DM + c];
    }
}

// ---------------- host launch ----------------
extern "C" void kernel_launch(void* const* d_in, const int* in_sizes, int n_in,
                              void* d_out, int out_size)
{
    float* S = nullptr;
    cudaGetSymbolAddress((void**)&S, g_scratch);

    float* pr    = S + OFF_PR;
    float* xln   = S + OFF_XLN;
    float* xz    = S + OFF_XZ;
    float* xc    = S + OFF_XC;
    float* xdbl  = S + OFF_XDBL;
    float* dtb   = S + OFF_DT;
    float* yb    = S + OFF_Y;
    float* catb  = S + OFF_CAT;
    float* fused = S + OFF_FUSED;

    const float* x        = (const float*)d_in[0];
    const float* fusion_w = (const float*)d_in[23];
    const float* fusion_b = (const float*)d_in[24];
    const int*   scan_idx = (const int*)d_in[25];
    const int*   inv_idx  = (const int*)d_in[26];

    gather_kernel<<<(ROWS*DM + 255)/256, 256>>>(x, scan_idx, pr);

    for (int dir = 0; dir < 2; dir++) {
        int base = 1 + dir * 11;
        const float* ln_g   = (const float*)d_in[base + 0];
        const float* ln_b   = (const float*)d_in[base + 1];
        const float* in_w   = (const float*)d_in[base + 2];   // (1536,384)
        const float* conv_w = (const float*)d_in[base + 3];   // (768,4)
        const float* conv_b = (const float*)d_in[base + 4];   // (768)
        const float* x_w    = (const float*)d_in[base + 5];   // (56,768)
        const float* dt_w   = (const float*)d_in[base + 6];   // (768,24)
        const float* dt_b   = (const float*)d_in[base + 7];   // (768)
        const float* A_log  = (const float*)d_in[base + 8];   // (768,16)
        const float* Dp     = (const float*)d_in[base + 9];   // (768)
        const float* out_w  = (const float*)d_in[base + 10];  // (384,768)

        ln_kernel<<<ROWS, 128>>>(pr, ln_g, ln_b, xln);

        // xz = xln @ in_w^T : (6144,384)x(384,1536)
        sgemm128<0><<<dim3(12, 48), 256>>>(xln, DM, in_w, DM,
                                           nullptr, nullptr, 0, xz, 2*DI);

        conv_kernel<<<(ROWS*DI + 255)/256, 256>>>(xz, conv_w, conv_b, xc, dir);

        // xdbl = xc @ x_w^T : (6144,768)x(768,56)
        sgemm_s<<<dim3(1, ROWS/32), 256>>>(xc, DI, x_w, DI, xdbl, XPD, XPD);

        // dt = softplus(dtr @ dt_w^T + dt_b) : (6144,24)x(24,768)
        sgemm128<2><<<dim3(6, 48), 256>>>(xdbl, XPD, dt_w, DTRK,
                                          dt_b, nullptr, 0, dtb, DI);

        scan_kernel<<<dim3(NB, 3), 256>>>(xc, dtb, xdbl, xz, A_log, Dp, yb, dir);

        // out_dir = y @ out_w^T + pr, stored into cat[:, dir*384] (ldc=768)
        sgemm128<3><<<dim3(3, 48), 256>>>(yb, DI, out_w, DI,
                                          nullptr, pr, DM,
                                          catb + dir * DM, 2*DM);
    }

    // fused = cat @ fusion_w^T + fusion_b : (6144,768)x(768,384)
    sgemm128<1><<<dim3(3, 48), 256>>>(catb, 2*DM, fusion_w, 2*DM,
                                      fusion_b, nullptr, 0, fused, DM);

    final_kernel<<<(NB*SEQF*DM + 255)/256, 256>>>(x, fused, inv_idx, (float*)d_out);
}

// round 4
// speedup vs baseline: 1.0828x; 1.0828x over previous
#include <cuda_runtime.h>
#include <cuda_bf16.h>
#include <math.h>

// ---------------- problem constants ----------------
#define NB    32
#define LSEQ  192
#define SEQF  193
#define DM    384
#define DI    768
#define DS    16
#define DTRK  24
#define XPD   56
#define ROWS  (NB*LSEQ)   // 6144

// ---------------- scratch (floats) ----------------
__device__ float g_scratch[43696128];

#define OFF_PR     0
#define OFF_XLN    2359296
#define OFF_XZ     4718592
#define OFF_XC     14155776
#define OFF_XDBL   18874368
#define OFF_DT     19218432
#define OFF_Y      23937024
#define OFF_CAT    28655616
#define OFF_FUSED  33374208
#define OFF_A3     35733504   // up to 6144*2304 bf16 = 7077888 floats
#define OFF_W3     42811392   // up to 1536*1152 bf16 = 884736 floats

// ---------------- gather ----------------
__global__ void gather_kernel(const float* __restrict__ X,
                              const int* __restrict__ scan_idx,
                              float* __restrict__ PR)
{
    int idx = blockIdx.x * blockDim.x + threadIdx.x;
    if (idx >= ROWS * DM) return;
    int c = idx % DM;
    int t = (idx / DM) % LSEQ;
    int b = idx / (DM * LSEQ);
    int src = scan_idx[t];
    PR[idx] = X[((size_t)b * SEQF + 1 + src) * DM + c];
}

// ---------------- layernorm ----------------
__global__ __launch_bounds__(128) void ln_kernel(const float* __restrict__ X,
                                                 const float* __restrict__ G,
                                                 const float* __restrict__ Bb,
                                                 float* __restrict__ Y)
{
    int row = blockIdx.x;
    const float* x = X + (size_t)row * DM;
    float v[3]; float s = 0.f, ss = 0.f;
    #pragma unroll
    for (int i = 0; i < 3; i++) {
        v[i] = x[threadIdx.x + i * 128];
        s += v[i]; ss += v[i] * v[i];
    }
    __shared__ float sh_s[4], sh_ss[4];
    #pragma unroll
    for (int o = 16; o; o >>= 1) {
        s  += __shfl_down_sync(0xffffffffu, s,  o);
        ss += __shfl_down_sync(0xffffffffu, ss, o);
    }
    int wid = threadIdx.x >> 5, lid = threadIdx.x & 31;
    if (lid == 0) { sh_s[wid] = s; sh_ss[wid] = ss; }
    __syncthreads();
    float ts = sh_s[0] + sh_s[1] + sh_s[2] + sh_s[3];
    float tss = sh_ss[0] + sh_ss[1] + sh_ss[2] + sh_ss[3];
    float mean = ts * (1.f / DM);
    float var = tss * (1.f / DM) - mean * mean;
    float rstd = rsqrtf(var + 1e-5f);
    float* y = Y + (size_t)row * DM;
    #pragma unroll
    for (int i = 0; i < 3; i++) {
        int c = threadIdx.x + i * 128;
        y[c] = (v[i] - mean) * rstd * G[c] + Bb[c];
    }
}

// ---------------- 3-block bf16 splits ----------------
// activations: Y[m, 3K] = [hi | hi | lo]
__global__ void split3_act(const float* __restrict__ X,
                           __nv_bfloat16* __restrict__ Y,
                           int total, int K)
{
    int idx = blockIdx.x * blockDim.x + threadIdx.x;
    if (idx >= total) return;
    int m = idx / K, k = idx % K;
    float x = X[idx];
    __nv_bfloat16 hi = __float2bfloat16(x);
    __nv_bfloat16 lo = __float2bfloat16(x - __bfloat162float(hi));
    size_t r = (size_t)m * (3 * K);
    Y[r + k]         = hi;
    Y[r + K + k]     = hi;
    Y[r + 2 * K + k] = lo;
}
// weights: Y[n, 3K] = [hi | lo | hi]
__global__ void split3_wt(const float* __restrict__ X,
                          __nv_bfloat16* __restrict__ Y,
                          int total, int K)
{
    int idx = blockIdx.x * blockDim.x + threadIdx.x;
    if (idx >= total) return;
    int m = idx / K, k = idx % K;
    float x = X[idx];
    __nv_bfloat16 hi = __float2bfloat16(x);
    __nv_bfloat16 lo = __float2bfloat16(x - __bfloat162float(hi));
    size_t r = (size_t)m * (3 * K);
    Y[r + k]         = hi;
    Y[r + K + k]     = lo;
    Y[r + 2 * K + k] = hi;
}

// ---------------- mma helpers ----------------
__device__ __forceinline__ void mma16816(float* c, const unsigned* a, const unsigned* b)
{
    asm volatile(
        "mma.sync.aligned.m16n8k16.row.col.f32.bf16.bf16.f32 "
        "{%0,%1,%2,%3}, {%4,%5,%6,%7}, {%8,%9}, {%0,%1,%2,%3};\n"
        : "+f"(c[0]), "+f"(c[1]), "+f"(c[2]), "+f"(c[3])
        : "r"(a[0]), "r"(a[1]), "r"(a[2]), "r"(a[3]), "r"(b[0]), "r"(b[1]));
}
__device__ __forceinline__ void ldsmx4(unsigned* r, unsigned addr)
{
    asm volatile("ldmatrix.sync.aligned.m8n8.x4.shared.b16 {%0,%1,%2,%3}, [%4];"
                 : "=r"(r[0]), "=r"(r[1]), "=r"(r[2]), "=r"(r[3]) : "r"(addr));
}
__device__ __forceinline__ void ldsmx2(unsigned* r, unsigned addr)
{
    asm volatile("ldmatrix.sync.aligned.m8n8.x2.shared.b16 {%0,%1}, [%2];"
                 : "=r"(r[0]), "=r"(r[1]) : "r"(addr));
}

// ---------------- bf16 tensor GEMM: C[M,N] = A2[M,K2] @ W2[N,K2]^T ----------------
// BM=128, BN=128, BK=32, 256 threads = 8 warps (2 x 4), warp tile 64x32.
// Requires M%128==0, N%128==0, K2%32==0.
// EPI: 0 none, 1 +bias, 3 +residual R
#define SKS 40
template<int EPI>
__global__ __launch_bounds__(256, 2) void bgemm(
    const __nv_bfloat16* __restrict__ A2, int lda,
    const __nv_bfloat16* __restrict__ W2, int K2,
    const float* __restrict__ bias,
    const float* __restrict__ R, int ldr,
    float* __restrict__ C, int ldc)
{
    __shared__ __nv_bfloat16 As[128 * SKS];
    __shared__ __nv_bfloat16 Ws[128 * SKS];

    int tid = threadIdx.x;
    int lane = tid & 31;
    int warp = tid >> 5;
    int rowBase = blockIdx.y * 128;
    int colBase = blockIdx.x * 128;
    int warpM = (warp >> 2) * 64;
    int warpN = (warp & 3) * 32;

    int id0 = tid, id1 = tid + 256;
    int r0 = id0 >> 2, c0 = (id0 & 3) * 8;
    int r1 = id1 >> 2, c1 = (id1 & 3) * 8;

    const __nv_bfloat16* Ap0 = A2 + (size_t)(rowBase + r0) * lda + c0;
    const __nv_bfloat16* Ap1 = A2 + (size_t)(rowBase + r1) * lda + c1;
    const __nv_bfloat16* Wp0 = W2 + (size_t)(colBase + r0) * K2 + c0;
    const __nv_bfloat16* Wp1 = W2 + (size_t)(colBase + r1) * K2 + c1;

    unsigned sA = (unsigned)__cvta_generic_to_shared(As);
    unsigned sW = (unsigned)__cvta_generic_to_shared(Ws);

    float acc[4][4][4];
    #pragma unroll
    for (int i = 0; i < 4; i++)
        #pragma unroll
        for (int j = 0; j < 4; j++)
            #pragma unroll
            for (int q = 0; q < 4; q++) acc[i][j][q] = 0.f;

    uint4 av0 = *(const uint4*)Ap0;
    uint4 av1 = *(const uint4*)Ap1;
    uint4 wv0 = *(const uint4*)Wp0;
    uint4 wv1 = *(const uint4*)Wp1;

    int l16 = lane & 15;
    unsigned aAddrBase = sA + ((warpM + l16) * SKS + (lane >> 4) * 8) * 2;
    unsigned wAddrBase = sW + ((warpN + (l16 & 7)) * SKS + ((l16 >> 3) & 1) * 8) * 2;

    for (int k0 = 0; k0 < K2; k0 += 32) {
        *(uint4*)&As[r0 * SKS + c0] = av0;
        *(uint4*)&As[r1 * SKS + c1] = av1;
        *(uint4*)&Ws[r0 * SKS + c0] = wv0;
        *(uint4*)&Ws[r1 * SKS + c1] = wv1;
        __syncthreads();

        if (k0 + 32 < K2) {
            av0 = *(const uint4*)(Ap0 + k0 + 32);
            av1 = *(const uint4*)(Ap1 + k0 + 32);
            wv0 = *(const uint4*)(Wp0 + k0 + 32);
            wv1 = *(const uint4*)(Wp1 + k0 + 32);
        }

        #pragma unroll
        for (int kk = 0; kk < 32; kk += 16) {
            unsigned b[4][2];
            #pragma unroll
            for (int j = 0; j < 4; j++)
                ldsmx2(b[j], wAddrBase + (j * 8 * SKS + kk) * 2);
            #pragma unroll
            for (int i = 0; i < 4; i++) {
                unsigned a[4];
                ldsmx4(a, aAddrBase + (i * 16 * SKS + kk) * 2);
                #pragma unroll
                for (int j = 0; j < 4; j++)
                    mma16816(acc[i][j], a, b[j]);
            }
        }
        __syncthreads();
    }

    int erow = lane >> 2;
    int ecol = (lane & 3) * 2;
    #pragma unroll
    for (int i = 0; i < 4; i++) {
        int row = rowBase + warpM + i * 16 + erow;
        #pragma unroll
        for (int j = 0; j < 4; j++) {
            int col = colBase + warpN + j * 8 + ecol;
            float v0 = acc[i][j][0], v1 = acc[i][j][1];
            float v2 = acc[i][j][2], v3 = acc[i][j][3];
            if (EPI == 1) {
                float b0 = bias[col], b1 = bias[col + 1];
                v0 += b0; v1 += b1; v2 += b0; v3 += b1;
            }
            if (EPI == 3) {
                v0 += R[(size_t)row * ldr + col];
                v1 += R[(size_t)row * ldr + col + 1];
                v2 += R[(size_t)(row + 8) * ldr + col];
                v3 += R[(size_t)(row + 8) * ldr + col + 1];
            }
            C[(size_t)row * ldc + col]           = v0;
            C[(size_t)row * ldc + col + 1]       = v1;
            C[(size_t)(row + 8) * ldc + col]     = v2;
            C[(size_t)(row + 8) * ldc + col + 1] = v3;
        }
    }
}

// ---------------- fp32 SGEMM (dt GEMM, K=24) ----------------
template<int EPI>
__global__ __launch_bounds__(256) void sgemm128(
    const float* __restrict__ A, int lda,
    const float* __restrict__ W, int K,
    const float* __restrict__ bias,
    float* __restrict__ C, int ldc)
{
    __shared__ float As[8][128];
    __shared__ float Ws[8][128];
    int tid = threadIdx.x;
    int rowBase = blockIdx.y * 128;
    int colBase = blockIdx.x * 128;
    int ty = tid >> 4, tx = tid & 15;
    int arow = tid >> 1;
    int ak   = (tid & 1) * 4;

    float acc[8][8];
    #pragma unroll
    for (int i = 0; i < 8; i++)
        #pragma unroll
        for (int j = 0; j < 8; j++) acc[i][j] = 0.f;

    const float* Aptr = A + (size_t)(rowBase + arow) * lda + ak;
    const float* Wptr = W + (size_t)(colBase + arow) * K + ak;

    for (int k0 = 0; k0 < K; k0 += 8) {
        float4 av = *(const float4*)(Aptr + k0);
        float4 wv = *(const float4*)(Wptr + k0);
        __syncthreads();
        As[ak+0][arow] = av.x; As[ak+1][arow] = av.y;
        As[ak+2][arow] = av.z; As[ak+3][arow] = av.w;
        Ws[ak+0][arow] = wv.x; Ws[ak+1][arow] = wv.y;
        Ws[ak+2][arow] = wv.z; Ws[ak+3][arow] = wv.w;
        __syncthreads();
        #pragma unroll
        for (int k = 0; k < 8; k++) {
            float a[8], w[8];
            *(float4*)&a[0] = *(const float4*)&As[k][ty*8];
            *(float4*)&a[4] = *(const float4*)&As[k][ty*8+4];
            *(float4*)&w[0] = *(const float4*)&Ws[k][tx*8];
            *(float4*)&w[4] = *(const float4*)&Ws[k][tx*8+4];
            #pragma unroll
            for (int i = 0; i < 8; i++)
                #pragma unroll
                for (int j = 0; j < 8; j++)
                    acc[i][j] = fmaf(a[i], w[j], acc[i][j]);
        }
    }
    #pragma unroll
    for (int i = 0; i < 8; i++) {
        int row = rowBase + ty * 8 + i;
        #pragma unroll
        for (int j = 0; j < 8; j++) {
            int col = colBase + tx * 8 + j;
            float v = acc[i][j];
            if (EPI == 2) {
                v += bias[col];
                v = (v > 20.f) ? v : log1pf(__expf(v));
            }
            C[(size_t)row * ldc + col] = v;
        }
    }
}

// ---------------- small-N GEMM (x_proj: N=56, K=768) ----------------
__global__ __launch_bounds__(256) void sgemm_s(
    const float* __restrict__ A, int lda,
    const float* __restrict__ W, int K,
    float* __restrict__ C, int ldc, int N)
{
    __shared__ float As[16][32];
    __shared__ float Ws[16][64];
    int tid = threadIdx.x;
    int rowBase = blockIdx.y * 32;
    int colBase = blockIdx.x * 64;
    int ty = tid >> 4, tx = tid & 15;
    float acc[2][4] = {{0.f,0.f,0.f,0.f},{0.f,0.f,0.f,0.f}};
    int wn = tid >> 2, wk = (tid & 3) * 4;
    bool wv = (colBase + wn) < N;

    for (int k0 = 0; k0 < K; k0 += 16) {
        __syncthreads();
        #pragma unroll
        for (int i = tid; i < 512; i += 256) {
            int r = i >> 4, k = i & 15;
            As[k][r] = A[(size_t)(rowBase + r) * lda + k0 + k];
        }
        float4 wvv = wv ? *(const float4*)&W[(size_t)(colBase + wn) * K + k0 + wk]
                        : make_float4(0.f,0.f,0.f,0.f);
        Ws[wk+0][wn] = wvv.x; Ws[wk+1][wn] = wvv.y;
        Ws[wk+2][wn] = wvv.z; Ws[wk+3][wn] = wvv.w;
        __syncthreads();
        #pragma unroll
        for (int k = 0; k < 16; k++) {
            float a0 = As[k][ty], a1 = As[k][ty + 16];
            float4 w4 = *(const float4*)&Ws[k][tx*4];
            acc[0][0] = fmaf(a0, w4.x, acc[0][0]);
            acc[0][1] = fmaf(a0, w4.y, acc[0][1]);
            acc[0][2] = fmaf(a0, w4.z, acc[0][2]);
            acc[0][3] = fmaf(a0, w4.w, acc[0][3]);
            acc[1][0] = fmaf(a1, w4.x, acc[1][0]);
            acc[1][1] = fmaf(a1, w4.y, acc[1][1]);
            acc[1][2] = fmaf(a1, w4.z, acc[1][2]);
            acc[1][3] = fmaf(a1, w4.w, acc[1][3]);
        }
    }
    #pragma unroll
    for (int i = 0; i < 2; i++) {
        int row = rowBase + ty + i * 16;
        #pragma unroll
        for (int j = 0; j < 4; j++) {
            int col = colBase + tx * 4 + j;
            if (col < N) C[(size_t)row * ldc + col] = acc[i][j];
        }
    }
}

// ---------------- causal depthwise conv (k=4) + SiLU ----------------
__global__ void conv_kernel(const float* __restrict__ XZ,
                            const float* __restrict__ Wc,
                            const float* __restrict__ Bc,
                            float* __restrict__ XC, int dir)
{
    int idx = blockIdx.x * blockDim.x + threadIdx.x;
    if (idx >= ROWS * DI) return;
    int d = idx % DI;
    int t = (idx / DI) % LSEQ;
    int b = idx / (DI * LSEQ);
    const float* xm = XZ + (size_t)b * LSEQ * (2 * DI) + d;
    float acc = Bc[d];
    #pragma unroll
    for (int j = 0; j < 4; j++) {
        int tt = (dir == 0) ? (t - 3 + j) : (t + 3 - j);
        if (tt >= 0 && tt < LSEQ)
            acc = fmaf(Wc[d * 4 + j], xm[(size_t)tt * (2 * DI)], acc);
    }
    acc = acc / (1.f + __expf(-acc));
    XC[idx] = acc;
}

// ---------------- selective scan ----------------
__global__ __launch_bounds__(256) void scan_kernel(
    const float* __restrict__ XC,
    const float* __restrict__ DT,
    const float* __restrict__ XDBL,
    const float* __restrict__ XZ,
    const float* __restrict__ Alog,
    const float* __restrict__ Dp,
    float* __restrict__ Y, int dir)
{
    __shared__ float Bs[LSEQ][DS];
    __shared__ float Cs[LSEQ][DS];
    int b = blockIdx.x;
    int d = blockIdx.y * 256 + threadIdx.x;

    const float* xd = XDBL + (size_t)b * LSEQ * XPD;
    for (int i = threadIdx.x; i < LSEQ * DS; i += 256) {
        int t = i / DS, n = i % DS;
        Bs[t][n] = xd[t * XPD + DTRK + n];
        Cs[t][n] = xd[t * XPD + DTRK + DS + n];
    }
    __syncthreads();

    float A[DS];
    #pragma unroll
    for (int n = 0; n < DS; n++) A[n] = -__expf(Alog[d * DS + n]);
    float Dd = Dp[d];
    float h[DS];
    #pragma unroll
    for (int n = 0; n < DS; n++) h[n] = 0.f;

    const float* ub  = XC + (size_t)b * LSEQ * DI + d;
    const float* dtb = DT + (size_t)b * LSEQ * DI + d;
    const float* zb  = XZ + (size_t)b * LSEQ * (2 * DI) + DI + d;
    float* yb = Y + (size_t)b * LSEQ * DI + d;

    for (int s = 0; s < LSEQ; s++) {
        int t = dir ? (LSEQ - 1 - s) : s;
        float dtv = dtb[(size_t)t * DI];
        float u   = ub[(size_t)t * DI];
        float du  = dtv * u;
        float accv = 0.f;
        #pragma unroll
        for (int n = 0; n < DS; n++) {
            float dA = __expf(dtv * A[n]);
            h[n] = fmaf(dA, h[n], du * Bs[t][n]);
            accv = fmaf(h[n], Cs[t][n], accv);
        }
        float z = zb[(size_t)t * (2 * DI)];
        float sz = z / (1.f + __expf(-z));
        yb[(size_t)t * DI] = (accv + u * Dd) * sz;
    }
}

// ---------------- final scatter ----------------
__global__ void final_kernel(const float* __restrict__ X,
                             const float* __restrict__ FUSED,
                             const int* __restrict__ inv_idx,
                             float* __restrict__ OUT)
{
    int idx = blockIdx.x * blockDim.x + threadIdx.x;
    if (idx >= NB * SEQF * DM) return;
    int c = idx % DM;
    int s = (idx / DM) % SEQF;
    int b = idx / (DM * SEQF);
    if (s == 0) {
        OUT[idx] = X[idx];
    } else {
        int src = inv_idx[s - 1];
        OUT[idx] = FUSED[((size_t)b * LSEQ + src) * DM + c];
    }
}

// ---------------- host launch ----------------
extern "C" void kernel_launch(void* const* d_in, const int* in_sizes, int n_in,
                              void* d_out, int out_size)
{
    float* S = nullptr;
    cudaGetSymbolAddress((void**)&S, g_scratch);

    float* pr    = S + OFF_PR;
    float* xln   = S + OFF_XLN;
    float* xz    = S + OFF_XZ;
    float* xc    = S + OFF_XC;
    float* xdbl  = S + OFF_XDBL;
    float* dtb   = S + OFF_DT;
    float* yb    = S + OFF_Y;
    float* catb  = S + OFF_CAT;
    float* fused = S + OFF_FUSED;
    __nv_bfloat16* a3 = (__nv_bfloat16*)(S + OFF_A3);
    __nv_bfloat16* w3 = (__nv_bfloat16*)(S + OFF_W3);

    const float* x        = (const float*)d_in[0];
    const float* fusion_w = (const float*)d_in[23];
    const float* fusion_b = (const float*)d_in[24];
    const int*   scan_idx = (const int*)d_in[25];
    const int*   inv_idx  = (const int*)d_in[26];

    gather_kernel<<<(ROWS*DM + 255)/256, 256>>>(x, scan_idx, pr);

    for (int dir = 0; dir < 2; dir++) {
        int base = 1 + dir * 11;
        const float* ln_g   = (const float*)d_in[base + 0];
        const float* ln_b   = (const float*)d_in[base + 1];
        const float* in_w   = (const float*)d_in[base + 2];   // (1536,384)
        const float* conv_w = (const float*)d_in[base + 3];
        const float* conv_b = (const float*)d_in[base + 4];
        const float* x_w    = (const float*)d_in[base + 5];   // (56,768)
        const float* dt_w   = (const float*)d_in[base + 6];   // (768,24)
        const float* dt_b   = (const float*)d_in[base + 7];
        const float* A_log  = (const float*)d_in[base + 8];
        const float* Dp     = (const float*)d_in[base + 9];
        const float* out_w  = (const float*)d_in[base + 10];  // (384,768)

        ln_kernel<<<ROWS, 128>>>(pr, ln_g, ln_b, xln);

        // in_proj: xz = xln @ in_w^T  via 3-block split bf16 (K'=1152)
        split3_act<<<(ROWS*DM + 255)/256, 256>>>(xln, a3, ROWS*DM, DM);
        split3_wt<<<(2*DI*DM + 255)/256, 256>>>(in_w, w3, 2*DI*DM, DM);
        bgemm<0><<<dim3(12, 48), 256>>>(a3, 3*DM, w3, 3*DM,
                                        nullptr, nullptr, 0, xz, 2*DI);

        conv_kernel<<<(ROWS*DI + 255)/256, 256>>>(xz, conv_w, conv_b, xc, dir);

        // x_proj (fp32, small N)
        sgemm_s<<<dim3(1, ROWS/32), 256>>>(xc, DI, x_w, DI, xdbl, XPD, XPD);

        // dt = softplus(dtr @ dt_w^T + dt_b)  (fp32, K=24)
        sgemm128<2><<<dim3(6, 48), 256>>>(xdbl, XPD, dt_w, DTRK, dt_b, dtb, DI);

        scan_kernel<<<dim3(NB, 3), 256>>>(xc, dtb, xdbl, xz, A_log, Dp, yb, dir);

        // out_proj: cat[:,dir*384+...] = y @ out_w^T + pr   (K'=2304)
        split3_act<<<(ROWS*DI + 255)/256, 256>>>(yb, a3, ROWS*DI, DI);
        split3_wt<<<(DM*DI + 255)/256, 256>>>(out_w, w3, DM*DI, DI);
        bgemm<3><<<dim3(3, 48), 256>>>(a3, 3*DI, w3, 3*DI,
                                       nullptr, pr, DM,
                                       catb + dir * DM, 2*DM);
    }

    // fusion: fused = cat @ fusion_w^T + fusion_b  (K'=2304)
    split3_act<<<(ROWS*DI + 255)/256, 256>>>(catb, a3, ROWS*DI, DI);
    split3_wt<<<(DM*DI + 255)/256, 256>>>(fusion_w, w3, DM*DI, DI);
    bgemm<1><<<dim3(3, 48), 256>>>(a3, 3*DI, w3, 3*DI,
                                   fusion_b, nullptr, 0, fused, DM);

    final_kernel<<<(NB*SEQF*DM + 255)/256, 256>>>(x, fused, inv_idx, (float*)d_out);
}

// round 7
// speedup vs baseline: 1.5816x; 1.4606x over previous
#include <cuda_runtime.h>
#include <cuda_bf16.h>
#include <math.h>

// ---------------- problem constants ----------------
#define NB    32
#define LSEQ  192
#define SEQF  193
#define DM    384
#define DI    768
#define DS    16
#define DTRK  24
#define XPD   56
#define ROWS  (NB*LSEQ)   // 6144

// ---------------- scratch (floats) ----------------
__device__ float g_scratch[43696128];

#define OFF_PR     0
#define OFF_XLN    2359296
#define OFF_XZ     4718592
#define OFF_XC     14155776
#define OFF_XDBL   18874368
#define OFF_DT     19218432
#define OFF_Y      23937024
#define OFF_CAT    28655616
#define OFF_FUSED  33374208
#define OFF_A3     35733504
#define OFF_W3     42811392

// ---------------- gather ----------------
__global__ void gather_kernel(const float* __restrict__ X,
                              const int* __restrict__ scan_idx,
                              float* __restrict__ PR)
{
    int idx = blockIdx.x * blockDim.x + threadIdx.x;
    if (idx >= ROWS * DM) return;
    int c = idx % DM;
    int t = (idx / DM) % LSEQ;
    int b = idx / (DM * LSEQ);
    int src = scan_idx[t];
    PR[idx] = X[((size_t)b * SEQF + 1 + src) * DM + c];
}

// ---------------- layernorm ----------------
__global__ __launch_bounds__(128) void ln_kernel(const float* __restrict__ X,
                                                 const float* __restrict__ G,
                                                 const float* __restrict__ Bb,
                                                 float* __restrict__ Y)
{
    int row = blockIdx.x;
    const float* x = X + (size_t)row * DM;
    float v[3]; float s = 0.f, ss = 0.f;
    #pragma unroll
    for (int i = 0; i < 3; i++) {
        v[i] = x[threadIdx.x + i * 128];
        s += v[i]; ss += v[i] * v[i];
    }
    __shared__ float sh_s[4], sh_ss[4];
    #pragma unroll
    for (int o = 16; o; o >>= 1) {
        s  += __shfl_down_sync(0xffffffffu, s,  o);
        ss += __shfl_down_sync(0xffffffffu, ss, o);
    }
    int wid = threadIdx.x >> 5, lid = threadIdx.x & 31;
    if (lid == 0) { sh_s[wid] = s; sh_ss[wid] = ss; }
    __syncthreads();
    float ts = sh_s[0] + sh_s[1] + sh_s[2] + sh_s[3];
    float tss = sh_ss[0] + sh_ss[1] + sh_ss[2] + sh_ss[3];
    float mean = ts * (1.f / DM);
    float var = tss * (1.f / DM) - mean * mean;
    float rstd = rsqrtf(var + 1e-5f);
    float* y = Y + (size_t)row * DM;
    #pragma unroll
    for (int i = 0; i < 3; i++) {
        int c = threadIdx.x + i * 128;
        y[c] = (v[i] - mean) * rstd * G[c] + Bb[c];
    }
}

// ---------------- 3-block bf16 splits ----------------
// activations: Y[m, 3K] = [hi | hi | lo] ; weights: Y[n, 3K] = [hi | lo | hi]
__global__ void split3_act(const float* __restrict__ X,
                           __nv_bfloat16* __restrict__ Y,
                           int total, int K)
{
    int idx = blockIdx.x * blockDim.x + threadIdx.x;
    if (idx >= total) return;
    int m = idx / K, k = idx % K;
    float x = X[idx];
    __nv_bfloat16 hi = __float2bfloat16(x);
    __nv_bfloat16 lo = __float2bfloat16(x - __bfloat162float(hi));
    size_t r = (size_t)m * (3 * K);
    Y[r + k]         = hi;
    Y[r + K + k]     = hi;
    Y[r + 2 * K + k] = lo;
}
__global__ void split3_wt(const float* __restrict__ X,
                          __nv_bfloat16* __restrict__ Y,
                          int total, int K)
{
    int idx = blockIdx.x * blockDim.x + threadIdx.x;
    if (idx >= total) return;
    int m = idx / K, k = idx % K;
    float x = X[idx];
    __nv_bfloat16 hi = __float2bfloat16(x);
    __nv_bfloat16 lo = __float2bfloat16(x - __bfloat162float(hi));
    size_t r = (size_t)m * (3 * K);
    Y[r + k]         = hi;
    Y[r + K + k]     = lo;
    Y[r + 2 * K + k] = hi;
}

// ---------------- mma / cp.async helpers ----------------
__device__ __forceinline__ void mma16816(float* c, const unsigned* a, const unsigned* b)
{
    asm volatile(
        "mma.sync.aligned.m16n8k16.row.col.f32.bf16.bf16.f32 "
        "{%0,%1,%2,%3}, {%4,%5,%6,%7}, {%8,%9}, {%0,%1,%2,%3};\n"
        : "+f"(c[0]), "+f"(c[1]), "+f"(c[2]), "+f"(c[3])
        : "r"(a[0]), "r"(a[1]), "r"(a[2]), "r"(a[3]), "r"(b[0]), "r"(b[1]));
}
__device__ __forceinline__ void ldsmx4(unsigned* r, unsigned addr)
{
    asm volatile("ldmatrix.sync.aligned.m8n8.x4.shared.b16 {%0,%1,%2,%3}, [%4];"
                 : "=r"(r[0]), "=r"(r[1]), "=r"(r[2]), "=r"(r[3]) : "r"(addr));
}
__device__ __forceinline__ void ldsmx2(unsigned* r, unsigned addr)
{
    asm volatile("ldmatrix.sync.aligned.m8n8.x2.shared.b16 {%0,%1}, [%2];"
                 : "=r"(r[0]), "=r"(r[1]) : "r"(addr));
}
__device__ __forceinline__ void cpa16(unsigned dst, const void* src)
{
    asm volatile("cp.async.cg.shared.global [%0], [%1], 16;\n" :: "r"(dst), "l"(src));
}
__device__ __forceinline__ void cpa_commit()
{
    asm volatile("cp.async.commit_group;\n");
}
template<int N>
__device__ __forceinline__ void cpa_wait()
{
    asm volatile("cp.async.wait_group %0;\n" :: "n"(N));
}

// ---------------- pipelined bf16 tensor GEMM: C[M,N] = A2[M,K2] @ W2[N,K2]^T --------
// BM=128, BN=128, BK=32, 256 threads = 8 warps (2x4), warp tile 64x32.
// 2-stage cp.async double buffering. M%128==0, N%128==0, K2%32==0.
// EPI: 0 none, 1 +bias, 3 +residual R
#define SKS 40
#define TILEB (128 * SKS * 2)   // bytes per smem tile buffer
template<int EPI>
__global__ __launch_bounds__(256, 2) void bgemm(
    const __nv_bfloat16* __restrict__ A2, int lda,
    const __nv_bfloat16* __restrict__ W2, int K2,
    const float* __restrict__ bias,
    const float* __restrict__ R, int ldr,
    float* __restrict__ C, int ldc)
{
    __shared__ __nv_bfloat16 As[2][128 * SKS];
    __shared__ __nv_bfloat16 Ws[2][128 * SKS];

    int tid = threadIdx.x;
    int lane = tid & 31;
    int warp = tid >> 5;
    int rowBase = blockIdx.y * 128;
    int colBase = blockIdx.x * 128;
    int warpM = (warp >> 2) * 64;
    int warpN = (warp & 3) * 32;

    int r0 = tid >> 2, c0 = (tid & 3) * 8;   // second row = r0 + 64
    const __nv_bfloat16* Ap0 = A2 + (size_t)(rowBase + r0) * lda + c0;
    const __nv_bfloat16* Ap1 = A2 + (size_t)(rowBase + r0 + 64) * lda + c0;
    const __nv_bfloat16* Wp0 = W2 + (size_t)(colBase + r0) * K2 + c0;
    const __nv_bfloat16* Wp1 = W2 + (size_t)(colBase + r0 + 64) * K2 + c0;

    unsigned sA = (unsigned)__cvta_generic_to_shared(&As[0][0]);
    unsigned sW = (unsigned)__cvta_generic_to_shared(&Ws[0][0]);
    unsigned stA0 = sA + (r0 * SKS + c0) * 2;
    unsigned stA1 = sA + ((r0 + 64) * SKS + c0) * 2;
    unsigned stW0 = sW + (r0 * SKS + c0) * 2;
    unsigned stW1 = sW + ((r0 + 64) * SKS + c0) * 2;

    float acc[4][4][4];
    #pragma unroll
    for (int i = 0; i < 4; i++)
        #pragma unroll
        for (int j = 0; j < 4; j++)
            #pragma unroll
            for (int q = 0; q < 4; q++) acc[i][j][q] = 0.f;

    int l16 = lane & 15;
    unsigned aAddrBase = sA + ((warpM + l16) * SKS + (lane >> 4) * 8) * 2;
    unsigned wAddrBase = sW + ((warpN + (l16 & 7)) * SKS + ((l16 >> 3) & 1) * 8) * 2;

    int nIter = K2 >> 5;   // K2/32

    // prologue: issue tile 0 into buffer 0
    cpa16(stA0, Ap0); cpa16(stA1, Ap1);
    cpa16(stW0, Wp0); cpa16(stW1, Wp1);
    cpa_commit();

    for (int it = 0; it < nIter; it++) {
        int buf = it & 1;
        if (it + 1 < nIter) {
            int nb = (it + 1) & 1;
            int ko = (it + 1) << 5;
            unsigned off = nb * TILEB;
            cpa16(stA0 + off, Ap0 + ko); cpa16(stA1 + off, Ap1 + ko);
            cpa16(stW0 + off, Wp0 + ko); cpa16(stW1 + off, Wp1 + ko);
            cpa_commit();
            cpa_wait<1>();
        } else {
            cpa_wait<0>();
        }
        __syncthreads();

        unsigned aB = aAddrBase + buf * TILEB;
        unsigned wB = wAddrBase + buf * TILEB;
        #pragma unroll
        for (int kk = 0; kk < 32; kk += 16) {
            unsigned b[4][2];
            #pragma unroll
            for (int j = 0; j < 4; j++)
                ldsmx2(b[j], wB + (j * 8 * SKS + kk) * 2);
            #pragma unroll
            for (int i = 0; i < 4; i++) {
                unsigned a[4];
                ldsmx4(a, aB + (i * 16 * SKS + kk) * 2);
                #pragma unroll
                for (int j = 0; j < 4; j++)
                    mma16816(acc[i][j], a, b[j]);
            }
        }
        __syncthreads();
    }

    int erow = lane >> 2;
    int ecol = (lane & 3) * 2;
    #pragma unroll
    for (int i = 0; i < 4; i++) {
        int row = rowBase + warpM + i * 16 + erow;
        #pragma unroll
        for (int j = 0; j < 4; j++) {
            int col = colBase + warpN + j * 8 + ecol;
            float v0 = acc[i][j][0], v1 = acc[i][j][1];
            float v2 = acc[i][j][2], v3 = acc[i][j][3];
            if (EPI == 1) {
                float b0 = bias[col], b1 = bias[col + 1];
                v0 += b0; v1 += b1; v2 += b0; v3 += b1;
            }
            if (EPI == 3) {
                v0 += R[(size_t)row * ldr + col];
                v1 += R[(size_t)row * ldr + col + 1];
                v2 += R[(size_t)(row + 8) * ldr + col];
                v3 += R[(size_t)(row + 8) * ldr + col + 1];
            }
            C[(size_t)row * ldc + col]           = v0;
            C[(size_t)row * ldc + col + 1]       = v1;
            C[(size_t)(row + 8) * ldc + col]     = v2;
            C[(size_t)(row + 8) * ldc + col + 1] = v3;
        }
    }
}

// ---------------- fp32 SGEMM (dt GEMM, K=24) ----------------
template<int EPI>
__global__ __launch_bounds__(256) void sgemm128(
    const float* __restrict__ A, int lda,
    const float* __restrict__ W, int K,
    const float* __restrict__ bias,
    float* __restrict__ C, int ldc)
{
    __shared__ float As[8][128];
    __shared__ float Ws[8][128];
    int tid = threadIdx.x;
    int rowBase = blockIdx.y * 128;
    int colBase = blockIdx.x * 128;
    int ty = tid >> 4, tx = tid & 15;
    int arow = tid >> 1;
    int ak   = (tid & 1) * 4;

    float acc[8][8];
    #pragma unroll
    for (int i = 0; i < 8; i++)
        #pragma unroll
        for (int j = 0; j < 8; j++) acc[i][j] = 0.f;

    const float* Aptr = A + (size_t)(rowBase + arow) * lda + ak;
    const float* Wptr = W + (size_t)(colBase + arow) * K + ak;

    for (int k0 = 0; k0 < K; k0 += 8) {
        float4 av = *(const float4*)(Aptr + k0);
        float4 wv = *(const float4*)(Wptr + k0);
        __syncthreads();
        As[ak+0][arow] = av.x; As[ak+1][arow] = av.y;
        As[ak+2][arow] = av.z; As[ak+3][arow] = av.w;
        Ws[ak+0][arow] = wv.x; Ws[ak+1][arow] = wv.y;
        Ws[ak+2][arow] = wv.z; Ws[ak+3][arow] = wv.w;
        __syncthreads();
        #pragma unroll
        for (int k = 0; k < 8; k++) {
            float a[8], w[8];
            *(float4*)&a[0] = *(const float4*)&As[k][ty*8];
            *(float4*)&a[4] = *(const float4*)&As[k][ty*8+4];
            *(float4*)&w[0] = *(const float4*)&Ws[k][tx*8];
            *(float4*)&w[4] = *(const float4*)&Ws[k][tx*8+4];
            #pragma unroll
            for (int i = 0; i < 8; i++)
                #pragma unroll
                for (int j = 0; j < 8; j++)
                    acc[i][j] = fmaf(a[i], w[j], acc[i][j]);
        }
    }
    #pragma unroll
    for (int i = 0; i < 8; i++) {
        int row = rowBase + ty * 8 + i;
        #pragma unroll
        for (int j = 0; j < 8; j++) {
            int col = colBase + tx * 8 + j;
            float v = acc[i][j];
            if (EPI == 2) {
                v += bias[col];
                v = (v > 20.f) ? v : log1pf(__expf(v));
            }
            C[(size_t)row * ldc + col] = v;
        }
    }
}

// ---------------- small-N GEMM (x_proj: N=56, K=768) ----------------
__global__ __launch_bounds__(256) void sgemm_s(
    const float* __restrict__ A, int lda,
    const float* __restrict__ W, int K,
    float* __restrict__ C, int ldc, int N)
{
    __shared__ float As[16][32];
    __shared__ float Ws[16][64];
    int tid = threadIdx.x;
    int rowBase = blockIdx.y * 32;
    int colBase = blockIdx.x * 64;
    int ty = tid >> 4, tx = tid & 15;
    float acc[2][4] = {{0.f,0.f,0.f,0.f},{0.f,0.f,0.f,0.f}};
    int wn = tid >> 2, wk = (tid & 3) * 4;
    bool wv = (colBase + wn) < N;

    for (int k0 = 0; k0 < K; k0 += 16) {
        __syncthreads();
        #pragma unroll
        for (int i = tid; i < 512; i += 256) {
            int r = i >> 4, k = i & 15;
            As[k][r] = A[(size_t)(rowBase + r) * lda + k0 + k];
        }
        float4 wvv = wv ? *(const float4*)&W[(size_t)(colBase + wn) * K + k0 + wk]
                        : make_float4(0.f,0.f,0.f,0.f);
        Ws[wk+0][wn] = wvv.x; Ws[wk+1][wn] = wvv.y;
        Ws[wk+2][wn] = wvv.z; Ws[wk+3][wn] = wvv.w;
        __syncthreads();
        #pragma unroll
        for (int k = 0; k < 16; k++) {
            float a0 = As[k][ty], a1 = As[k][ty + 16];
            float4 w4 = *(const float4*)&Ws[k][tx*4];
            acc[0][0] = fmaf(a0, w4.x, acc[0][0]);
            acc[0][1] = fmaf(a0, w4.y, acc[0][1]);
            acc[0][2] = fmaf(a0, w4.z, acc[0][2]);
            acc[0][3] = fmaf(a0, w4.w, acc[0][3]);
            acc[1][0] = fmaf(a1, w4.x, acc[1][0]);
            acc[1][1] = fmaf(a1, w4.y, acc[1][1]);
            acc[1][2] = fmaf(a1, w4.z, acc[1][2]);
            acc[1][3] = fmaf(a1, w4.w, acc[1][3]);
        }
    }
    #pragma unroll
    for (int i = 0; i < 2; i++) {
        int row = rowBase + ty + i * 16;
        #pragma unroll
        for (int j = 0; j < 4; j++) {
            int col = colBase + tx * 4 + j;
            if (col < N) C[(size_t)row * ldc + col] = acc[i][j];
        }
    }
}

// ---------------- causal depthwise conv (k=4) + SiLU ----------------
__global__ void conv_kernel(const float* __restrict__ XZ,
                            const float* __restrict__ Wc,
                            const float* __restrict__ Bc,
                            float* __restrict__ XC, int dir)
{
    int idx = blockIdx.x * blockDim.x + threadIdx.x;
    if (idx >= ROWS * DI) return;
    int d = idx % DI;
    int t = (idx / DI) % LSEQ;
    int b = idx / (DI * LSEQ);
    const float* xm = XZ + (size_t)b * LSEQ * (2 * DI) + d;
    float acc = Bc[d];
    #pragma unroll
    for (int j = 0; j < 4; j++) {
        int tt = (dir == 0) ? (t - 3 + j) : (t + 3 - j);
        if (tt >= 0 && tt < LSEQ)
            acc = fmaf(Wc[d * 4 + j], xm[(size_t)tt * (2 * DI)], acc);
    }
    acc = acc / (1.f + __expf(-acc));
    XC[idx] = acc;
}

// ---------------- selective scan (128 thr, grid (NB,6)) ----------------
__global__ __launch_bounds__(128) void scan_kernel(
    const float* __restrict__ XC,
    const float* __restrict__ DT,
    const float* __restrict__ XDBL,
    const float* __restrict__ XZ,
    const float* __restrict__ Alog,
    const float* __restrict__ Dp,
    float* __restrict__ Y, int dir)
{
    __shared__ float Bs[LSEQ][DS];
    __shared__ float Cs[LSEQ][DS];
    int b = blockIdx.x;
    int d = blockIdx.y * 128 + threadIdx.x;

    const float* xd = XDBL + (size_t)b * LSEQ * XPD;
    for (int i = threadIdx.x; i < LSEQ * DS; i += 128) {
        int t = i / DS, n = i % DS;
        Bs[t][n] = xd[t * XPD + DTRK + n];
        Cs[t][n] = xd[t * XPD + DTRK + DS + n];
    }
    __syncthreads();

    float A[DS];
    #pragma unroll
    for (int n = 0; n < DS; n++) A[n] = -__expf(Alog[d * DS + n]);
    float Dd = Dp[d];
    float h[DS];
    #pragma unroll
    for (int n = 0; n < DS; n++) h[n] = 0.f;

    const float* ub  = XC + (size_t)b * LSEQ * DI + d;
    const float* dtb = DT + (size_t)b * LSEQ * DI + d;
    const float* zb  = XZ + (size_t)b * LSEQ * (2 * DI) + DI + d;
    float* yb = Y + (size_t)b * LSEQ * DI + d;

    for (int s = 0; s < LSEQ; s++) {
        int t = dir ? (LSEQ - 1 - s) : s;
        float dtv = dtb[(size_t)t * DI];
        float u   = ub[(size_t)t * DI];
        float du  = dtv * u;
        float accv = 0.f;
        #pragma unroll
        for (int n = 0; n < DS; n++) {
            float dA = __expf(dtv * A[n]);
            h[n] = fmaf(dA, h[n], du * Bs[t][n]);
            accv = fmaf(h[n], Cs[t][n], accv);
        }
        float z = zb[(size_t)t * (2 * DI)];
        float sz = z / (1.f + __expf(-z));
        yb[(size_t)t * DI] = (accv + u * Dd) * sz;
    }
}

// ---------------- final scatter ----------------
__global__ void final_kernel(const float* __restrict__ X,
                             const float* __restrict__ FUSED,
                             const int* __restrict__ inv_idx,
                             float* __restrict__ OUT)
{
    int idx = blockIdx.x * blockDim.x + threadIdx.x;
    if (idx >= NB * SEQF * DM) return;
    int c = idx % DM;
    int s = (idx / DM) % SEQF;
    int b = idx / (DM * SEQF);
    if (s == 0) {
        OUT[idx] = X[idx];
    } else {
        int src = inv_idx[s - 1];
        OUT[idx] = FUSED[((size_t)b * LSEQ + src) * DM + c];
    }
}

// ---------------- host launch ----------------
extern "C" void kernel_launch(void* const* d_in, const int* in_sizes, int n_in,
                              void* d_out, int out_size)
{
    float* S = nullptr;
    cudaGetSymbolAddress((void**)&S, g_scratch);

    float* pr    = S + OFF_PR;
    float* xln   = S + OFF_XLN;
    float* xz    = S + OFF_XZ;
    float* xc    = S + OFF_XC;
    float* xdbl  = S + OFF_XDBL;
    float* dtb   = S + OFF_DT;
    float* yb    = S + OFF_Y;
    float* catb  = S + OFF_CAT;
    float* fused = S + OFF_FUSED;
    __nv_bfloat16* a3 = (__nv_bfloat16*)(S + OFF_A3);
    __nv_bfloat16* w3 = (__nv_bfloat16*)(S + OFF_W3);

    const float* x        = (const float*)d_in[0];
    const float* fusion_w = (const float*)d_in[23];
    const float* fusion_b = (const float*)d_in[24];
    const int*   scan_idx = (const int*)d_in[25];
    const int*   inv_idx  = (const int*)d_in[26];

    gather_kernel<<<(ROWS*DM + 255)/256, 256>>>(x, scan_idx, pr);

    for (int dir = 0; dir < 2; dir++) {
        int base = 1 + dir * 11;
        const float* ln_g   = (const float*)d_in[base + 0];
        const float* ln_b   = (const float*)d_in[base + 1];
        const float* in_w   = (const float*)d_in[base + 2];   // (1536,384)
        const float* conv_w = (const float*)d_in[base + 3];
        const float* conv_b = (const float*)d_in[base + 4];
        const float* x_w    = (const float*)d_in[base + 5];   // (56,768)
        const float* dt_w   = (const float*)d_in[base + 6];   // (768,24)
        const float* dt_b   = (const float*)d_in[base + 7];
        const float* A_log  = (const float*)d_in[base + 8];
        const float* Dp     = (const float*)d_in[base + 9];
        const float* out_w  = (const float*)d_in[base + 10];  // (384,768)

        ln_kernel<<<ROWS, 128>>>(pr, ln_g, ln_b, xln);

        // in_proj: xz = xln @ in_w^T  via 3-block split bf16 (K'=1152)
        split3_act<<<(ROWS*DM + 255)/256, 256>>>(xln, a3, ROWS*DM, DM);
        split3_wt<<<(2*DI*DM + 255)/256, 256>>>(in_w, w3, 2*DI*DM, DM);
        bgemm<0><<<dim3(12, 48), 256>>>(a3, 3*DM, w3, 3*DM,
                                        nullptr, nullptr, 0, xz, 2*DI);

        conv_kernel<<<(ROWS*DI + 255)/256, 256>>>(xz, conv_w, conv_b, xc, dir);

        // x_proj (fp32, small N)
        sgemm_s<<<dim3(1, ROWS/32), 256>>>(xc, DI, x_w, DI, xdbl, XPD, XPD);

        // dt = softplus(dtr @ dt_w^T + dt_b)  (fp32, K=24)
        sgemm128<2><<<dim3(6, 48), 256>>>(xdbl, XPD, dt_w, DTRK, dt_b, dtb, DI);

        scan_kernel<<<dim3(NB, 6), 128>>>(xc, dtb, xdbl, xz, A_log, Dp, yb, dir);

        // out_proj: cat[:,dir*384+...] = y @ out_w^T + pr   (K'=2304)
        split3_act<<<(ROWS*DI + 255)/256, 256>>>(yb, a3, ROWS*DI, DI);
        split3_wt<<<(DM*DI + 255)/256, 256>>>(out_w, w3, DM*DI, DI);
        bgemm<3><<<dim3(3, 48), 256>>>(a3, 3*DI, w3, 3*DI,
                                       nullptr, pr, DM,
                                       catb + dir * DM, 2*DM);
    }

    // fusion: fused = cat @ fusion_w^T + fusion_b  (K'=2304)
    split3_act<<<(ROWS*DI + 255)/256, 256>>>(catb, a3, ROWS*DI, DI);
    split3_wt<<<(DM*DI + 255)/256, 256>>>(fusion_w, w3, DM*DI, DI);
    bgemm<1><<<dim3(3, 48), 256>>>(a3, 3*DI, w3, 3*DI,
                                   fusion_b, nullptr, 0, fused, DM);

    final_kernel<<<(NB*SEQF*DM + 255)/256, 256>>>(x, fused, inv_idx, (float*)d_out);
}

// round 8
// speedup vs baseline: 1.6630x; 1.0515x over previous
#include <cuda_runtime.h>
#include <cuda_bf16.h>
#include <math.h>

// ---------------- problem constants ----------------
#define NB    32
#define LSEQ  192
#define SEQF  193
#define DM    384
#define DI    768
#define DS    16
#define DTRK  24
#define XPD   56
#define ROWS  (NB*LSEQ)   // 6144

// ---------------- scratch (floats) ----------------
__device__ float g_scratch[43696128];

#define OFF_PR     0            // 2359296
#define OFF_XZ     2359296      // 9437184
#define OFF_XC     11796480     // 4718592
#define OFF_XDBL   16515072     // 344064
#define OFF_DT     16859136     // 4718592
#define OFF_FUSED  21577728     // 2359296
#define OFF_ACT3   23937024     // 7077888 floats = 14155776 bf16
#define OFF_CAT3   31014912     // 7077888 floats
#define OFF_W3     38092800     // 884736 floats

// ---------------- gather ----------------
__global__ void gather_kernel(const float* __restrict__ X,
                              const int* __restrict__ scan_idx,
                              float* __restrict__ PR)
{
    int idx = blockIdx.x * blockDim.x + threadIdx.x;
    if (idx >= ROWS * DM) return;
    int c = idx % DM;
    int t = (idx / DM) % LSEQ;
    int b = idx / (DM * LSEQ);
    int src = scan_idx[t];
    PR[idx] = X[((size_t)b * SEQF + 1 + src) * DM + c];
}

// ---------------- layernorm fused with 3-block bf16 split ----------------
// out row (len 3*DM bf16): [hi | hi | lo]
__global__ __launch_bounds__(128) void ln_split_kernel(
    const float* __restrict__ X,
    const float* __restrict__ G,
    const float* __restrict__ Bb,
    __nv_bfloat16* __restrict__ A3)
{
    int row = blockIdx.x;
    const float* x = X + (size_t)row * DM;
    float v[3]; float s = 0.f, ss = 0.f;
    #pragma unroll
    for (int i = 0; i < 3; i++) {
        v[i] = x[threadIdx.x + i * 128];
        s += v[i]; ss += v[i] * v[i];
    }
    __shared__ float sh_s[4], sh_ss[4];
    #pragma unroll
    for (int o = 16; o; o >>= 1) {
        s  += __shfl_down_sync(0xffffffffu, s,  o);
        ss += __shfl_down_sync(0xffffffffu, ss, o);
    }
    int wid = threadIdx.x >> 5, lid = threadIdx.x & 31;
    if (lid == 0) { sh_s[wid] = s; sh_ss[wid] = ss; }
    __syncthreads();
    float ts = sh_s[0] + sh_s[1] + sh_s[2] + sh_s[3];
    float tss = sh_ss[0] + sh_ss[1] + sh_ss[2] + sh_ss[3];
    float mean = ts * (1.f / DM);
    float var = tss * (1.f / DM) - mean * mean;
    float rstd = rsqrtf(var + 1e-5f);
    __nv_bfloat16* a = A3 + (size_t)row * (3 * DM);
    #pragma unroll
    for (int i = 0; i < 3; i++) {
        int c = threadIdx.x + i * 128;
        float y = (v[i] - mean) * rstd * G[c] + Bb[c];
        __nv_bfloat16 hi = __float2bfloat16(y);
        __nv_bfloat16 lo = __float2bfloat16(y - __bfloat162float(hi));
        a[c]          = hi;
        a[DM + c]     = hi;
        a[2 * DM + c] = lo;
    }
}

// ---------------- weight 3-block split: Y[n, 3K] = [hi | lo | hi] ----------------
__global__ void split3_wt(const float* __restrict__ X,
                          __nv_bfloat16* __restrict__ Y,
                          int total, int K)
{
    int idx = blockIdx.x * blockDim.x + threadIdx.x;
    if (idx >= total) return;
    int m = idx / K, k = idx % K;
    float x = X[idx];
    __nv_bfloat16 hi = __float2bfloat16(x);
    __nv_bfloat16 lo = __float2bfloat16(x - __bfloat162float(hi));
    size_t r = (size_t)m * (3 * K);
    Y[r + k]         = hi;
    Y[r + K + k]     = lo;
    Y[r + 2 * K + k] = hi;
}

// ---------------- mma / cp.async helpers ----------------
__device__ __forceinline__ void mma16816(float* c, const unsigned* a, const unsigned* b)
{
    asm volatile(
        "mma.sync.aligned.m16n8k16.row.col.f32.bf16.bf16.f32 "
        "{%0,%1,%2,%3}, {%4,%5,%6,%7}, {%8,%9}, {%0,%1,%2,%3};\n"
        : "+f"(c[0]), "+f"(c[1]), "+f"(c[2]), "+f"(c[3])
        : "r"(a[0]), "r"(a[1]), "r"(a[2]), "r"(a[3]), "r"(b[0]), "r"(b[1]));
}
__device__ __forceinline__ void ldsmx4(unsigned* r, unsigned addr)
{
    asm volatile("ldmatrix.sync.aligned.m8n8.x4.shared.b16 {%0,%1,%2,%3}, [%4];"
                 : "=r"(r[0]), "=r"(r[1]), "=r"(r[2]), "=r"(r[3]) : "r"(addr));
}
__device__ __forceinline__ void ldsmx2(unsigned* r, unsigned addr)
{
    asm volatile("ldmatrix.sync.aligned.m8n8.x2.shared.b16 {%0,%1}, [%2];"
                 : "=r"(r[0]), "=r"(r[1]) : "r"(addr));
}
__device__ __forceinline__ void cpa16(unsigned dst, const void* src)
{
    asm volatile("cp.async.cg.shared.global [%0], [%1], 16;\n" :: "r"(dst), "l"(src));
}
__device__ __forceinline__ void cpa_commit()
{
    asm volatile("cp.async.commit_group;\n");
}
template<int N>
__device__ __forceinline__ void cpa_wait()
{
    asm volatile("cp.async.wait_group %0;\n" :: "n"(N));
}

// ---------------- 3-stage pipelined bf16 tensor GEMM ----------------
// C = A3[M,K2] @ W3[N,K2]^T. BM=128, BN=128, BK=32, 8 warps, warp tile 64x32.
// One __syncthreads per K-iter; prefetch distance 2. Dynamic smem 61440B.
// EPI: 0 none (fp32 C), 1 +bias (fp32 C), 3 +residual then split-bf16 store to C3
#define SKS 40
#define TILEB (128 * SKS * 2)
#define STAGES 3
template<int EPI>
__global__ __launch_bounds__(256, 2) void bgemm(
    const __nv_bfloat16* __restrict__ A2, int lda,
    const __nv_bfloat16* __restrict__ W2, int K2,
    const float* __restrict__ bias,
    const float* __restrict__ R, int ldr,
    float* __restrict__ C, int ldc,
    __nv_bfloat16* __restrict__ C3, int dirOff)
{
    extern __shared__ __nv_bfloat16 dsm[];
    __nv_bfloat16* Asm = dsm;                       // [STAGES][128*SKS]
    __nv_bfloat16* Wsm = dsm + STAGES * 128 * SKS;

    int tid = threadIdx.x;
    int lane = tid & 31;
    int warp = tid >> 5;
    int rowBase = blockIdx.y * 128;
    int colBase = blockIdx.x * 128;
    int warpM = (warp >> 2) * 64;
    int warpN = (warp & 3) * 32;

    int r0 = tid >> 2, c0 = (tid & 3) * 8;
    const __nv_bfloat16* Ap0 = A2 + (size_t)(rowBase + r0) * lda + c0;
    const __nv_bfloat16* Ap1 = A2 + (size_t)(rowBase + r0 + 64) * lda + c0;
    const __nv_bfloat16* Wp0 = W2 + (size_t)(colBase + r0) * K2 + c0;
    const __nv_bfloat16* Wp1 = W2 + (size_t)(colBase + r0 + 64) * K2 + c0;

    unsigned sA = (unsigned)__cvta_generic_to_shared(Asm);
    unsigned sW = (unsigned)__cvta_generic_to_shared(Wsm);
    unsigned stA0 = sA + (r0 * SKS + c0) * 2;
    unsigned stA1 = sA + ((r0 + 64) * SKS + c0) * 2;
    unsigned stW0 = sW + (r0 * SKS + c0) * 2;
    unsigned stW1 = sW + ((r0 + 64) * SKS + c0) * 2;

    float acc[4][4][4];
    #pragma unroll
    for (int i = 0; i < 4; i++)
        #pragma unroll
        for (int j = 0; j < 4; j++)
            #pragma unroll
            for (int q = 0; q < 4; q++) acc[i][j][q] = 0.f;

    int l16 = lane & 15;
    unsigned aAddrBase = sA + ((warpM + l16) * SKS + (lane >> 4) * 8) * 2;
    unsigned wAddrBase = sW + ((warpN + (l16 & 7)) * SKS + ((l16 >> 3) & 1) * 8) * 2;

    int nIter = K2 >> 5;

    // prologue: tiles 0 and 1
    cpa16(stA0, Ap0); cpa16(stA1, Ap1);
    cpa16(stW0, Wp0); cpa16(stW1, Wp1);
    cpa_commit();
    {
        unsigned off = TILEB;
        cpa16(stA0 + off, Ap0 + 32); cpa16(stA1 + off, Ap1 + 32);
        cpa16(stW0 + off, Wp0 + 32); cpa16(stW1 + off, Wp1 + 32);
        cpa_commit();
    }

    int bufc = 0, bufn = 2;
    for (int it = 0; it < nIter; it++) {
        if (it + 1 < nIter) cpa_wait<1>(); else cpa_wait<0>();
        __syncthreads();
        if (it + 2 < nIter) {
            int ko = (it + 2) << 5;
            unsigned off = bufn * TILEB;
            cpa16(stA0 + off, Ap0 + ko); cpa16(stA1 + off, Ap1 + ko);
            cpa16(stW0 + off, Wp0 + ko); cpa16(stW1 + off, Wp1 + ko);
            cpa_commit();
        }

        unsigned aB = aAddrBase + bufc * TILEB;
        unsigned wB = wAddrBase + bufc * TILEB;
        #pragma unroll
        for (int kk = 0; kk < 32; kk += 16) {
            unsigned b[4][2];
            #pragma unroll
            for (int j = 0; j < 4; j++)
                ldsmx2(b[j], wB + (j * 8 * SKS + kk) * 2);
            #pragma unroll
            for (int i = 0; i < 4; i++) {
                unsigned a[4];
                ldsmx4(a, aB + (i * 16 * SKS + kk) * 2);
                #pragma unroll
                for (int j = 0; j < 4; j++)
                    mma16816(acc[i][j], a, b[j]);
            }
        }
        bufc = (bufc + 1 == STAGES) ? 0 : bufc + 1;
        bufn = (bufn + 1 == STAGES) ? 0 : bufn + 1;
    }

    int erow = lane >> 2;
    int ecol = (lane & 3) * 2;
    #pragma unroll
    for (int i = 0; i < 4; i++) {
        int row = rowBase + warpM + i * 16 + erow;
        #pragma unroll
        for (int j = 0; j < 4; j++) {
            int col = colBase + warpN + j * 8 + ecol;
            float v0 = acc[i][j][0], v1 = acc[i][j][1];
            float v2 = acc[i][j][2], v3 = acc[i][j][3];
            if (EPI == 1) {
                float b0 = bias[col], b1 = bias[col + 1];
                v0 += b0; v1 += b1; v2 += b0; v3 += b1;
            }
            if (EPI == 3) {
                // residual add (pr), then split-bf16 store into C3 (row len 2304)
                v0 += R[(size_t)row * ldr + col];
                v1 += R[(size_t)row * ldr + col + 1];
                v2 += R[(size_t)(row + 8) * ldr + col];
                v3 += R[(size_t)(row + 8) * ldr + col + 1];
                int colL = dirOff + col;
                #pragma unroll
                for (int h = 0; h < 2; h++) {
                    float s0 = (h == 0) ? v0 : v2;
                    float s1 = (h == 0) ? v1 : v3;
                    int rr = row + h * 8;
                    __nv_bfloat16 h0 = __float2bfloat16(s0);
                    __nv_bfloat16 h1 = __float2bfloat16(s1);
                    __nv_bfloat16 l0 = __float2bfloat16(s0 - __bfloat162float(h0));
                    __nv_bfloat16 l1 = __float2bfloat16(s1 - __bfloat162float(h1));
                    __nv_bfloat162 hp; hp.x = h0; hp.y = h1;
                    __nv_bfloat162 lp; lp.x = l0; lp.y = l1;
                    size_t rb = (size_t)rr * 2304;
                    *(__nv_bfloat162*)&C3[rb + colL]        = hp;
                    *(__nv_bfloat162*)&C3[rb + 768 + colL]  = hp;
                    *(__nv_bfloat162*)&C3[rb + 1536 + colL] = lp;
                }
            } else {
                C[(size_t)row * ldc + col]           = v0;
                C[(size_t)row * ldc + col + 1]       = v1;
                C[(size_t)(row + 8) * ldc + col]     = v2;
                C[(size_t)(row + 8) * ldc + col + 1] = v3;
            }
        }
    }
}

// ---------------- fp32 SGEMM (dt GEMM, K=24) ----------------
template<int EPI>
__global__ __launch_bounds__(256) void sgemm128(
    const float* __restrict__ A, int lda,
    const float* __restrict__ W, int K,
    const float* __restrict__ bias,
    float* __restrict__ C, int ldc)
{
    __shared__ float As[8][128];
    __shared__ float Ws[8][128];
    int tid = threadIdx.x;
    int rowBase = blockIdx.y * 128;
    int colBase = blockIdx.x * 128;
    int ty = tid >> 4, tx = tid & 15;
    int arow = tid >> 1;
    int ak   = (tid & 1) * 4;

    float acc[8][8];
    #pragma unroll
    for (int i = 0; i < 8; i++)
        #pragma unroll
        for (int j = 0; j < 8; j++) acc[i][j] = 0.f;

    const float* Aptr = A + (size_t)(rowBase + arow) * lda + ak;
    const float* Wptr = W + (size_t)(colBase + arow) * K + ak;

    for (int k0 = 0; k0 < K; k0 += 8) {
        float4 av = *(const float4*)(Aptr + k0);
        float4 wv = *(const float4*)(Wptr + k0);
        __syncthreads();
        As[ak+0][arow] = av.x; As[ak+1][arow] = av.y;
        As[ak+2][arow] = av.z; As[ak+3][arow] = av.w;
        Ws[ak+0][arow] = wv.x; Ws[ak+1][arow] = wv.y;
        Ws[ak+2][arow] = wv.z; Ws[ak+3][arow] = wv.w;
        __syncthreads();
        #pragma unroll
        for (int k = 0; k < 8; k++) {
            float a[8], w[8];
            *(float4*)&a[0] = *(const float4*)&As[k][ty*8];
            *(float4*)&a[4] = *(const float4*)&As[k][ty*8+4];
            *(float4*)&w[0] = *(const float4*)&Ws[k][tx*8];
            *(float4*)&w[4] = *(const float4*)&Ws[k][tx*8+4];
            #pragma unroll
            for (int i = 0; i < 8; i++)
                #pragma unroll
                for (int j = 0; j < 8; j++)
                    acc[i][j] = fmaf(a[i], w[j], acc[i][j]);
        }
    }
    #pragma unroll
    for (int i = 0; i < 8; i++) {
        int row = rowBase + ty * 8 + i;
        #pragma unroll
        for (int j = 0; j < 8; j++) {
            int col = colBase + tx * 8 + j;
            float v = acc[i][j];
            if (EPI == 2) {
                v += bias[col];
                v = (v > 20.f) ? v : log1pf(__expf(v));
            }
            C[(size_t)row * ldc + col] = v;
        }
    }
}

// ---------------- small-N GEMM (x_proj: N=56, K=768) ----------------
__global__ __launch_bounds__(256) void sgemm_s(
    const float* __restrict__ A, int lda,
    const float* __restrict__ W, int K,
    float* __restrict__ C, int ldc, int N)
{
    __shared__ float As[16][32];
    __shared__ float Ws[16][64];
    int tid = threadIdx.x;
    int rowBase = blockIdx.y * 32;
    int colBase = blockIdx.x * 64;
    int ty = tid >> 4, tx = tid & 15;
    float acc[2][4] = {{0.f,0.f,0.f,0.f},{0.f,0.f,0.f,0.f}};
    int wn = tid >> 2, wk = (tid & 3) * 4;
    bool wv = (colBase + wn) < N;

    for (int k0 = 0; k0 < K; k0 += 16) {
        __syncthreads();
        #pragma unroll
        for (int i = tid; i < 512; i += 256) {
            int r = i >> 4, k = i & 15;
            As[k][r] = A[(size_t)(rowBase + r) * lda + k0 + k];
        }
        float4 wvv = wv ? *(const float4*)&W[(size_t)(colBase + wn) * K + k0 + wk]
                        : make_float4(0.f,0.f,0.f,0.f);
        Ws[wk+0][wn] = wvv.x; Ws[wk+1][wn] = wvv.y;
        Ws[wk+2][wn] = wvv.z; Ws[wk+3][wn] = wvv.w;
        __syncthreads();
        #pragma unroll
        for (int k = 0; k < 16; k++) {
            float a0 = As[k][ty], a1 = As[k][ty + 16];
            float4 w4 = *(const float4*)&Ws[k][tx*4];
            acc[0][0] = fmaf(a0, w4.x, acc[0][0]);
            acc[0][1] = fmaf(a0, w4.y, acc[0][1]);
            acc[0][2] = fmaf(a0, w4.z, acc[0][2]);
            acc[0][3] = fmaf(a0, w4.w, acc[0][3]);
            acc[1][0] = fmaf(a1, w4.x, acc[1][0]);
            acc[1][1] = fmaf(a1, w4.y, acc[1][1]);
            acc[1][2] = fmaf(a1, w4.z, acc[1][2]);
            acc[1][3] = fmaf(a1, w4.w, acc[1][3]);
        }
    }
    #pragma unroll
    for (int i = 0; i < 2; i++) {
        int row = rowBase + ty + i * 16;
        #pragma unroll
        for (int j = 0; j < 4; j++) {
            int col = colBase + tx * 4 + j;
            if (col < N) C[(size_t)row * ldc + col] = acc[i][j];
        }
    }
}

// ---------------- causal depthwise conv (k=4) + SiLU ----------------
__global__ void conv_kernel(const float* __restrict__ XZ,
                            const float* __restrict__ Wc,
                            const float* __restrict__ Bc,
                            float* __restrict__ XC, int dir)
{
    int idx = blockIdx.x * blockDim.x + threadIdx.x;
    if (idx >= ROWS * DI) return;
    int d = idx % DI;
    int t = (idx / DI) % LSEQ;
    int b = idx / (DI * LSEQ);
    const float* xm = XZ + (size_t)b * LSEQ * (2 * DI) + d;
    float acc = Bc[d];
    #pragma unroll
    for (int j = 0; j < 4; j++) {
        int tt = (dir == 0) ? (t - 3 + j) : (t + 3 - j);
        if (tt >= 0 && tt < LSEQ)
            acc = fmaf(Wc[d * 4 + j], xm[(size_t)tt * (2 * DI)], acc);
    }
    acc = acc / (1.f + __expf(-acc));
    XC[idx] = acc;
}

// ---------------- selective scan, fused with gate + bf16 split output ----------------
// out: A3 rows of len 3*DI = [hi | hi | lo]
__global__ __launch_bounds__(128) void scan_kernel(
    const float* __restrict__ XC,
    const float* __restrict__ DT,
    const float* __restrict__ XDBL,
    const float* __restrict__ XZ,
    const float* __restrict__ Alog,
    const float* __restrict__ Dp,
    __nv_bfloat16* __restrict__ A3, int dir)
{
    __shared__ float Bs[LSEQ][DS];
    __shared__ float Cs[LSEQ][DS];
    int b = blockIdx.x;
    int d = blockIdx.y * 128 + threadIdx.x;

    const float* xd = XDBL + (size_t)b * LSEQ * XPD;
    for (int i = threadIdx.x; i < LSEQ * DS; i += 128) {
        int t = i / DS, n = i % DS;
        Bs[t][n] = xd[t * XPD + DTRK + n];
        Cs[t][n] = xd[t * XPD + DTRK + DS + n];
    }
    __syncthreads();

    float A[DS];
    #pragma unroll
    for (int n = 0; n < DS; n++) A[n] = -__expf(Alog[d * DS + n]);
    float Dd = Dp[d];
    float h[DS];
    #pragma unroll
    for (int n = 0; n < DS; n++) h[n] = 0.f;

    const float* ub  = XC + (size_t)b * LSEQ * DI + d;
    const float* dtb = DT + (size_t)b * LSEQ * DI + d;
    const float* zb  = XZ + (size_t)b * LSEQ * (2 * DI) + DI + d;

    for (int s = 0; s < LSEQ; s++) {
        int t = dir ? (LSEQ - 1 - s) : s;
        float dtv = dtb[(size_t)t * DI];
        float u   = ub[(size_t)t * DI];
        float du  = dtv * u;
        float accv = 0.f;
        #pragma unroll
        for (int n = 0; n < DS; n++) {
            float dA = __expf(dtv * A[n]);
            h[n] = fmaf(dA, h[n], du * Bs[t][n]);
            accv = fmaf(h[n], Cs[t][n], accv);
        }
        float z = zb[(size_t)t * (2 * DI)];
        float sz = z / (1.f + __expf(-z));
        float y = (accv + u * Dd) * sz;
        __nv_bfloat16 hi = __float2bfloat16(y);
        __nv_bfloat16 lo = __float2bfloat16(y - __bfloat162float(hi));
        size_t rb = ((size_t)b * LSEQ + t) * (3 * DI);
        A3[rb + d]          = hi;
        A3[rb + DI + d]     = hi;
        A3[rb + 2 * DI + d] = lo;
    }
}

// ---------------- final scatter ----------------
__global__ void final_kernel(const float* __restrict__ X,
                             const float* __restrict__ FUSED,
                             const int* __restrict__ inv_idx,
                             float* __restrict__ OUT)
{
    int idx = blockIdx.x * blockDim.x + threadIdx.x;
    if (idx >= NB * SEQF * DM) return;
    int c = idx % DM;
    int s = (idx / DM) % SEQF;
    int b = idx / (DM * SEQF);
    if (s == 0) {
        OUT[idx] = X[idx];
    } else {
        int src = inv_idx[s - 1];
        OUT[idx] = FUSED[((size_t)b * LSEQ + src) * DM + c];
    }
}

// ---------------- host launch ----------------
extern "C" void kernel_launch(void* const* d_in, const int* in_sizes, int n_in,
                              void* d_out, int out_size)
{
    float* S = nullptr;
    cudaGetSymbolAddress((void**)&S, g_scratch);

    float* pr    = S + OFF_PR;
    float* xz    = S + OFF_XZ;
    float* xc    = S + OFF_XC;
    float* xdbl  = S + OFF_XDBL;
    float* dtb   = S + OFF_DT;
    float* fused = S + OFF_FUSED;
    __nv_bfloat16* a3   = (__nv_bfloat16*)(S + OFF_ACT3);
    __nv_bfloat16* cat3 = (__nv_bfloat16*)(S + OFF_CAT3);
    __nv_bfloat16* w3   = (__nv_bfloat16*)(S + OFF_W3);

    const int SMEM_BG = STAGES * 128 * SKS * 2 * 2;   // 61440 bytes
    cudaFuncSetAttribute(bgemm<0>, cudaFuncAttributeMaxDynamicSharedMemorySize, SMEM_BG);
    cudaFuncSetAttribute(bgemm<1>, cudaFuncAttributeMaxDynamicSharedMemorySize, SMEM_BG);
    cudaFuncSetAttribute(bgemm<3>, cudaFuncAttributeMaxDynamicSharedMemorySize, SMEM_BG);

    const float* x        = (const float*)d_in[0];
    const float* fusion_w = (const float*)d_in[23];
    const float* fusion_b = (const float*)d_in[24];
    const int*   scan_idx = (const int*)d_in[25];
    const int*   inv_idx  = (const int*)d_in[26];

    gather_kernel<<<(ROWS*DM + 255)/256, 256>>>(x, scan_idx, pr);

    for (int dir = 0; dir < 2; dir++) {
        int base = 1 + dir * 11;
        const float* ln_g   = (const float*)d_in[base + 0];
        const float* ln_b   = (const float*)d_in[base + 1];
        const float* in_w   = (const float*)d_in[base + 2];   // (1536,384)
        const float* conv_w = (const float*)d_in[base + 3];
        const float* conv_b = (const float*)d_in[base + 4];
        const float* x_w    = (const float*)d_in[base + 5];   // (56,768)
        const float* dt_w   = (const float*)d_in[base + 6];   // (768,24)
        const float* dt_b   = (const float*)d_in[base + 7];
        const float* A_log  = (const float*)d_in[base + 8];
        const float* Dp     = (const float*)d_in[base + 9];
        const float* out_w  = (const float*)d_in[base + 10];  // (384,768)

        // LN fused with act split (in_proj A, K'=1152)
        ln_split_kernel<<<ROWS, 128>>>(pr, ln_g, ln_b, a3);

        // in_proj: xz = xln @ in_w^T
        split3_wt<<<(2*DI*DM + 255)/256, 256>>>(in_w, w3, 2*DI*DM, DM);
        bgemm<0><<<dim3(12, 48), 256, SMEM_BG>>>(a3, 3*DM, w3, 3*DM,
                                                 nullptr, nullptr, 0, xz, 2*DI,
                                                 nullptr, 0);

        conv_kernel<<<(ROWS*DI + 255)/256, 256>>>(xz, conv_w, conv_b, xc, dir);

        // x_proj (fp32, small N)
        sgemm_s<<<dim3(1, ROWS/32), 256>>>(xc, DI, x_w, DI, xdbl, XPD, XPD);

        // dt = softplus(dtr @ dt_w^T + dt_b)  (fp32, K=24)
        sgemm128<2><<<dim3(6, 48), 256>>>(xdbl, XPD, dt_w, DTRK, dt_b, dtb, DI);

        // scan fused with gate + act split (out_proj A, K'=2304)
        scan_kernel<<<dim3(NB, 6), 128>>>(xc, dtb, xdbl, xz, A_log, Dp, a3, dir);

        // out_proj: cat3[:, dir cols] = split(y @ out_w^T + pr)
        split3_wt<<<(DM*DI + 255)/256, 256>>>(out_w, w3, DM*DI, DI);
        bgemm<3><<<dim3(3, 48), 256, SMEM_BG>>>(a3, 3*DI, w3, 3*DI,
                                                nullptr, pr, DM, nullptr, 0,
                                                cat3, dir * DM);
    }

    // fusion: fused = cat @ fusion_w^T + fusion_b  (K'=2304)
    split3_wt<<<(DM*DI + 255)/256, 256>>>(fusion_w, w3, DM*DI, DI);
    bgemm<1><<<dim3(3, 48), 256, SMEM_BG>>>(cat3, 2304, w3, 3*(2*DM),
                                            fusion_b, nullptr, 0, fused, DM,
                                            nullptr, 0);

    final_kernel<<<(NB*SEQF*DM + 255)/256, 256>>>(x, fused, inv_idx, (float*)d_out);
}